// round 15
// baseline (speedup 1.0000x reference)
#include <cuda_runtime.h>
#include <cuda_bf16.h>
#include <cstdint>

#define NB      8
#define SEQ     1024
#define HIDDEN  1024
#define NHEADS  16
#define DHEAD   64
#define MTOT    (NB*SEQ)        // 8192
#define SZTERM  1.024e-5f       // S * ZERO = 1024 * 1e-8

// ---------------- scratch (no allocations allowed) ----------------
__device__ float g_ctx[NB*SEQ*HIDDEN];             // [b][s][h*64+d]
__device__ __nv_bfloat16 g_ah[MTOT*HIDDEN];        // GEMM A hi
__device__ __nv_bfloat16 g_al[MTOT*HIDDEN];        // GEMM A lo
__device__ __nv_bfloat16 g_wh[HIDDEN*HIDDEN];      // W hi
__device__ __nv_bfloat16 g_wl[HIDDEN*HIDDEN];      // W lo
__device__ __nv_bfloat16 g_qh[NB*NHEADS*SEQ*DHEAD];  // [b][h][s][d] splits
__device__ __nv_bfloat16 g_ql[NB*NHEADS*SEQ*DHEAD];
__device__ __nv_bfloat16 g_kh[NB*NHEADS*SEQ*DHEAD];
__device__ __nv_bfloat16 g_kl[NB*NHEADS*SEQ*DHEAD];
__device__ __nv_bfloat16 g_vh[NB*NHEADS*SEQ*DHEAD];
__device__ __nv_bfloat16 g_vl[NB*NHEADS*SEQ*DHEAD];

// ================= helpers =================
__device__ __forceinline__ uint32_t smem_u32(const void* p) {
    uint32_t a;
    asm("{ .reg .u64 t; cvta.to.shared.u64 t, %1; cvt.u32.u64 %0, t; }" : "=r"(a) : "l"(p));
    return a;
}
__device__ __forceinline__ void cp_async16(uint32_t dst, const void* src) {
    asm volatile("cp.async.cg.shared.global [%0], [%1], 16;" :: "r"(dst), "l"(src) : "memory");
}
#define CP_COMMIT()  asm volatile("cp.async.commit_group;" ::: "memory")
#define CP_WAIT(n)   asm volatile("cp.async.wait_group %0;" :: "n"(n) : "memory")

#define SWZ128(o) ((o) ^ (((o) >> 3) & 0x70))

#define LDMX4(r, a) \
    asm volatile("ldmatrix.sync.aligned.m8n8.x4.shared.b16 {%0,%1,%2,%3}, [%4];" \
        : "=r"((r)[0]), "=r"((r)[1]), "=r"((r)[2]), "=r"((r)[3]) : "r"(a))

#define LDMX4T(r, a) \
    asm volatile("ldmatrix.sync.aligned.m8n8.x4.trans.shared.b16 {%0,%1,%2,%3}, [%4];" \
        : "=r"((r)[0]), "=r"((r)[1]), "=r"((r)[2]), "=r"((r)[3]) : "r"(a))

#define MMA16816(c, a, b) \
    asm volatile("mma.sync.aligned.m16n8k16.row.col.f32.bf16.bf16.f32 " \
        "{%0,%1,%2,%3}, {%4,%5,%6,%7}, {%8,%9}, {%0,%1,%2,%3};" \
        : "+f"((c)[0]), "+f"((c)[1]), "+f"((c)[2]), "+f"((c)[3]) \
        : "r"((a)[0]), "r"((a)[1]), "r"((a)[2]), "r"((a)[3]), "r"((b)[0]), "r"((b)[1]))

#define MMA2(c0, c1, a, r4) do { \
    uint32_t _b0[2] = {(r4)[0], (r4)[1]}; \
    uint32_t _b1[2] = {(r4)[2], (r4)[3]}; \
    MMA16816(c0, a, _b0); \
    MMA16816(c1, a, _b1); \
} while (0)

__device__ __forceinline__ uint32_t pack_bf2(__nv_bfloat16 x, __nv_bfloat16 y) {
    __nv_bfloat162 t = __halves2bfloat162(x, y);
    return *(uint32_t*)&t;
}
__device__ __forceinline__ void split_pair(float x, float y, uint32_t& hi, uint32_t& lo) {
    __nv_bfloat16 hx = __float2bfloat16_rn(x);
    __nv_bfloat16 hy = __float2bfloat16_rn(y);
    hi = pack_bf2(hx, hy);
    lo = pack_bf2(__float2bfloat16_rn(x - __bfloat162float(hx)),
                  __float2bfloat16_rn(y - __bfloat162float(hy)));
}

// ================= fp32 -> bf16 hi/lo split (2 float4/thread) =================
__global__ __launch_bounds__(256)
void split_bf16(const float* __restrict__ x, __nv_bfloat16* __restrict__ hi,
                __nv_bfloat16* __restrict__ lo, int n4)
{
    const int i0 = blockIdx.x * 512 + threadIdx.x;
#pragma unroll
    for (int r = 0; r < 2; r++) {
        const int i = i0 + r*256;
        if (i >= n4) return;
        float4 v = ((const float4*)x)[i];
        float f[4] = {v.x, v.y, v.z, v.w};
        __nv_bfloat16 h[4], l[4];
#pragma unroll
        for (int j = 0; j < 4; j++) {
            h[j] = __float2bfloat16_rn(f[j]);
            l[j] = __float2bfloat16_rn(f[j] - __bfloat162float(h[j]));
        }
        __nv_bfloat162* H = (__nv_bfloat162*)hi;
        __nv_bfloat162* L = (__nv_bfloat162*)lo;
        H[2*i]   = __halves2bfloat162(h[0], h[1]);
        H[2*i+1] = __halves2bfloat162(h[2], h[3]);
        L[2*i]   = __halves2bfloat162(l[0], l[1]);
        L[2*i+1] = __halves2bfloat162(l[2], l[3]);
    }
}

// ================= mma.sync GEMM: C = A[M,K] @ W[N,K]^T + bias =================
// mode 0: fp32 output [m][n];  mode 1: bf16 hi/lo split output in [b][h][s][d]
#define TILE_BYTES 16384u
#define STAGE_BYTES (4u*TILE_BYTES)
#define TC_SMEM (3u*STAGE_BYTES)         // 196608

__device__ __forceinline__ void load_chunk(
    const __nv_bfloat16* __restrict__ Ah, const __nv_bfloat16* __restrict__ Al,
    const __nv_bfloat16* __restrict__ Bh, const __nv_bfloat16* __restrict__ Bl,
    int m0, int n0, int kc, uint32_t buf, int tid)
{
#pragma unroll
    for (int it = 0; it < 4; it++) {
        const int idx = tid + it*256;
        const int row = idx >> 3;
        const int c   = idx & 7;
        const uint32_t off = SWZ128((uint32_t)(row*128 + c*16));
        const size_t arow = (size_t)(m0 + row) * HIDDEN + kc*64 + c*8;
        const size_t brow = (size_t)(n0 + row) * HIDDEN + kc*64 + c*8;
        cp_async16(buf + 0*TILE_BYTES + off, Ah + arow);
        cp_async16(buf + 1*TILE_BYTES + off, Al + arow);
        cp_async16(buf + 2*TILE_BYTES + off, Bh + brow);
        cp_async16(buf + 3*TILE_BYTES + off, Bl + brow);
    }
    CP_COMMIT();
}

__global__ __launch_bounds__(256, 1)
void tcgemm(const __nv_bfloat16* __restrict__ Ah, const __nv_bfloat16* __restrict__ Al,
            const __nv_bfloat16* __restrict__ Bh, const __nv_bfloat16* __restrict__ Bl,
            const float* __restrict__ bias, float* __restrict__ Cf,
            __nv_bfloat16* __restrict__ Ch, __nv_bfloat16* __restrict__ Cl, int mode)
{
    extern __shared__ char smem[];
    const uint32_t sb = smem_u32(smem);
    const int tid  = threadIdx.x;
    const int lane = tid & 31;
    const int wid  = tid >> 5;
    const int m0 = blockIdx.y * 128;
    const int n0 = blockIdx.x * 128;
    const int wm = (wid & 1) * 64;
    const int wn = (wid >> 1) * 32;

    const int a_row = wm + (lane & 15);
    const int a_kh  = (lane >> 4) * 16;
    const int b_rr  = (lane & 7) + ((lane >> 4) << 3);
    const int b_kh  = (lane & 8) ? 16 : 0;

    float acc[4][4][4];
#pragma unroll
    for (int mt = 0; mt < 4; mt++)
#pragma unroll
        for (int nt = 0; nt < 4; nt++)
#pragma unroll
            for (int j = 0; j < 4; j++) acc[mt][nt][j] = 0.0f;

#pragma unroll
    for (int s = 0; s < 3; s++)
        load_chunk(Ah, Al, Bh, Bl, m0, n0, s, sb + s*STAGE_BYTES, tid);

    for (int i = 0; i < 16; i++) {
        if (i < 14)       CP_WAIT(2);
        else if (i == 14) CP_WAIT(1);
        else              CP_WAIT(0);
        __syncthreads();

        const uint32_t buf = sb + (uint32_t)(i % 3) * STAGE_BYTES;
        const uint32_t bAh = buf;
        const uint32_t bAl = buf + 1*TILE_BYTES;
        const uint32_t bBh = buf + 2*TILE_BYTES;
        const uint32_t bBl = buf + 3*TILE_BYTES;

#pragma unroll
        for (int ks = 0; ks < 4; ks++) {
            const int kb = ks * 32;
            uint32_t aH[4][4], aL[4][4], bH[4][2], bL[4][2];
#pragma unroll
            for (int mt = 0; mt < 4; mt++) {
                const uint32_t ao = SWZ128((uint32_t)((a_row + mt*16)*128 + kb + a_kh));
                LDMX4(aH[mt], bAh + ao);
                LDMX4(aL[mt], bAl + ao);
            }
#pragma unroll
            for (int p = 0; p < 2; p++) {
                const uint32_t bo = SWZ128((uint32_t)((wn + p*16 + b_rr)*128 + kb + b_kh));
                uint32_t rh[4], rl[4];
                LDMX4(rh, bBh + bo);
                LDMX4(rl, bBl + bo);
                bH[2*p][0] = rh[0]; bH[2*p][1] = rh[1];
                bH[2*p+1][0] = rh[2]; bH[2*p+1][1] = rh[3];
                bL[2*p][0] = rl[0]; bL[2*p][1] = rl[1];
                bL[2*p+1][0] = rl[2]; bL[2*p+1][1] = rl[3];
            }
            // product-outermost passes: 16 independent MMAs per pass,
            // same-accumulator reuse distance = 16 (RAW latency hidden)
#pragma unroll
            for (int mt = 0; mt < 4; mt++)
#pragma unroll
                for (int nt = 0; nt < 4; nt++)
                    MMA16816(acc[mt][nt], aH[mt], bH[nt]);
#pragma unroll
            for (int mt = 0; mt < 4; mt++)
#pragma unroll
                for (int nt = 0; nt < 4; nt++)
                    MMA16816(acc[mt][nt], aH[mt], bL[nt]);
#pragma unroll
            for (int mt = 0; mt < 4; mt++)
#pragma unroll
                for (int nt = 0; nt < 4; nt++)
                    MMA16816(acc[mt][nt], aL[mt], bH[nt]);
        }
        __syncthreads();
        if (i + 3 < 16)
            load_chunk(Ah, Al, Bh, Bl, m0, n0, i + 3, buf, tid);
    }

#pragma unroll
    for (int mt = 0; mt < 4; mt++) {
        const int r0 = wm + mt*16 + (lane >> 2);
#pragma unroll
        for (int half = 0; half < 2; half++) {
            const int m  = m0 + r0 + half*8;
            const int bb = m >> 10;
            const int ss = m & 1023;
#pragma unroll
            for (int nt = 0; nt < 4; nt++) {
                const int n = n0 + wn + nt*8 + 2*(lane & 3);
                float v0 = acc[mt][nt][half*2+0] + bias[n];
                float v1 = acc[mt][nt][half*2+1] + bias[n+1];
                if (mode == 1) {
                    const int hh = n >> 6;
                    const int d  = n & 63;
                    const size_t idx = (((size_t)(bb*NHEADS + hh))*SEQ + ss)*DHEAD + d;
                    __nv_bfloat16 h0 = __float2bfloat16_rn(v0);
                    __nv_bfloat16 h1 = __float2bfloat16_rn(v1);
                    *(__nv_bfloat162*)(Ch + idx) = __halves2bfloat162(h0, h1);
                    *(__nv_bfloat162*)(Cl + idx) = __halves2bfloat162(
                        __float2bfloat16_rn(v0 - __bfloat162float(h0)),
                        __float2bfloat16_rn(v1 - __bfloat162float(h1)));
                } else {
                    *(float2*)(Cf + (size_t)m * HIDDEN + n) = make_float2(v0, v1);
                }
            }
        }
    }
}

// ================= tensor-core flash attention =================
// CTA: 128 q rows x one (b,h). 8 warps, warp = 16 q rows x 128 keys.
#define AT_STAGE 66048u
#define AT_SMEM  (32768u + 2u*AT_STAGE)   // 164864

__device__ __forceinline__ void load_kv(
    uint32_t st, const __nv_bfloat16* __restrict__ Kh_, const __nv_bfloat16* __restrict__ Kl_,
    const __nv_bfloat16* __restrict__ Vh_, const __nv_bfloat16* __restrict__ Vl_,
    const float* __restrict__ Kmask, int bh, int b, int kt, int tid)
{
    const size_t koff = ((size_t)bh*SEQ + kt)*DHEAD;
#pragma unroll
    for (int it = 0; it < 4; it++) {
        const int idx = tid + it*256;
        const int row = idx >> 3;
        const int c   = idx & 7;
        const uint32_t off = SWZ128((uint32_t)(row*128 + c*16));
        const size_t src = koff + (size_t)row*DHEAD + c*8;
        cp_async16(st + 0u*16384u + off, Kh_ + src);
        cp_async16(st + 1u*16384u + off, Kl_ + src);
        cp_async16(st + 2u*16384u + off, Vh_ + src);
        cp_async16(st + 3u*16384u + off, Vl_ + src);
    }
    if (tid < 32)
        cp_async16(st + 65536u + tid*16, Kmask + (size_t)b*SEQ + kt + tid*4);
    CP_COMMIT();
}

__global__ __launch_bounds__(256, 1)
void flash_mma(const __nv_bfloat16* __restrict__ Qh_, const __nv_bfloat16* __restrict__ Ql_,
               const __nv_bfloat16* __restrict__ Kh_, const __nv_bfloat16* __restrict__ Kl_,
               const __nv_bfloat16* __restrict__ Vh_, const __nv_bfloat16* __restrict__ Vl_,
               const float* __restrict__ Qmask, const float* __restrict__ Kmask,
               float* __restrict__ Ctx)
{
    extern __shared__ char smem[];
    const uint32_t sb = smem_u32(smem);
    const int tid  = threadIdx.x;
    const int lane = tid & 31;
    const int wid  = tid >> 5;
    const int q0 = blockIdx.x * 128;
    const int h  = blockIdx.y;
    const int b  = blockIdx.z;
    const int bh = b*NHEADS + h;

    {
        const size_t qoff = ((size_t)bh*SEQ + q0)*DHEAD;
#pragma unroll
        for (int it = 0; it < 4; it++) {
            const int idx = tid + it*256;
            const int row = idx >> 3;
            const int c   = idx & 7;
            const uint32_t off = SWZ128((uint32_t)(row*128 + c*16));
            const size_t src = qoff + (size_t)row*DHEAD + c*8;
            cp_async16(sb + off, Qh_ + src);
            cp_async16(sb + 16384u + off, Ql_ + src);
        }
        CP_COMMIT();
    }
    load_kv(sb + 32768u,             Kh_, Kl_, Vh_, Vl_, Kmask, bh, b, 0,   tid);
    load_kv(sb + 32768u + AT_STAGE,  Kh_, Kl_, Vh_, Vl_, Kmask, bh, b, 128, tid);

    const int a_row = (wid << 4) + (lane & 15);
    const int a_kh  = (lane >> 4) * 16;
    const int b_rr  = (lane & 7) + ((lane >> 4) << 3);
    const int b_kh  = (lane & 8) ? 16 : 0;

    uint32_t qH[4][4], qL[4][4];
    float O[8][4];
#pragma unroll
    for (int nt = 0; nt < 8; nt++)
#pragma unroll
        for (int j = 0; j < 4; j++) O[nt][j] = 0.0f;
    float m0 = -1e30f, m1 = -1e30f, l0 = 0.f, l1 = 0.f, lm0 = 0.f, lm1 = 0.f;

    for (int i = 0; i < 8; i++) {
        CP_WAIT(1);
        __syncthreads();

        if (i == 0) {
#pragma unroll
            for (int ks = 0; ks < 4; ks++) {
                const uint32_t ao = SWZ128((uint32_t)(a_row*128 + ks*32 + a_kh));
                LDMX4(qH[ks], sb + ao);
                LDMX4(qL[ks], sb + 16384u + ao);
            }
        }

        const uint32_t st = sb + 32768u + (uint32_t)(i & 1)*AT_STAGE;
        const float* Kms = (const float*)(smem + 32768u + (uint32_t)(i & 1)*AT_STAGE + 65536u);

        // ---- S = QhKh + QhKl + QlKh : group 4 key-tiles, product-outer passes ----
        float S[16][4];
#pragma unroll
        for (int nt = 0; nt < 16; nt++)
#pragma unroll
            for (int j = 0; j < 4; j++) S[nt][j] = 0.0f;

#pragma unroll
        for (int ks = 0; ks < 4; ks++) {
#pragma unroll
            for (int pg = 0; pg < 2; pg++) {
                uint32_t rh[4][4], rl[4][4];
#pragma unroll
                for (int j = 0; j < 4; j++) {
                    const int p = pg*4 + j;
                    const uint32_t bo = SWZ128((uint32_t)((p*16 + b_rr)*128 + ks*32 + b_kh));
                    LDMX4(rh[j], st + bo);
                    LDMX4(rl[j], st + 16384u + bo);
                }
                // pass HH (8 independent), then HL, then LH
#pragma unroll
                for (int j = 0; j < 4; j++) {
                    const int p = pg*4 + j;
                    MMA2(S[2*p], S[2*p+1], qH[ks], rh[j]);
                }
#pragma unroll
                for (int j = 0; j < 4; j++) {
                    const int p = pg*4 + j;
                    MMA2(S[2*p], S[2*p+1], qH[ks], rl[j]);
                }
#pragma unroll
                for (int j = 0; j < 4; j++) {
                    const int p = pg*4 + j;
                    MMA2(S[2*p], S[2*p+1], qL[ks], rh[j]);
                }
            }
        }

        // ---- online softmax ----
        float mx0 = -1e30f, mx1 = -1e30f;
#pragma unroll
        for (int nt = 0; nt < 16; nt++) {
            S[nt][0] *= 8.0f; S[nt][1] *= 8.0f; S[nt][2] *= 8.0f; S[nt][3] *= 8.0f;
            mx0 = fmaxf(mx0, fmaxf(S[nt][0], S[nt][1]));
            mx1 = fmaxf(mx1, fmaxf(S[nt][2], S[nt][3]));
        }
        mx0 = fmaxf(mx0, __shfl_xor_sync(0xffffffffu, mx0, 1));
        mx0 = fmaxf(mx0, __shfl_xor_sync(0xffffffffu, mx0, 2));
        mx1 = fmaxf(mx1, __shfl_xor_sync(0xffffffffu, mx1, 1));
        mx1 = fmaxf(mx1, __shfl_xor_sync(0xffffffffu, mx1, 2));

        const float mn0 = fmaxf(m0, mx0), mn1 = fmaxf(m1, mx1);
        const float f0 = __expf(m0 - mn0), f1 = __expf(m1 - mn1);
        float sl0 = 0.f, slm0 = 0.f, sl1 = 0.f, slm1 = 0.f;
#pragma unroll
        for (int nt = 0; nt < 16; nt++) {
            const float kma = Kms[nt*8 + 2*(lane & 3)];
            const float kmb = Kms[nt*8 + 2*(lane & 3) + 1];
            float e0 = __expf(S[nt][0] - mn0); sl0 += e0; float p0 = e0*kma; slm0 += p0; S[nt][0] = p0;
            float e1 = __expf(S[nt][1] - mn0); sl0 += e1; float p1 = e1*kmb; slm0 += p1; S[nt][1] = p1;
            float e2 = __expf(S[nt][2] - mn1); sl1 += e2; float p2 = e2*kma; slm1 += p2; S[nt][2] = p2;
            float e3 = __expf(S[nt][3] - mn1); sl1 += e3; float p3 = e3*kmb; slm1 += p3; S[nt][3] = p3;
        }
#pragma unroll
        for (int o = 1; o <= 2; o <<= 1) {
            sl0  += __shfl_xor_sync(0xffffffffu, sl0,  o);
            slm0 += __shfl_xor_sync(0xffffffffu, slm0, o);
            sl1  += __shfl_xor_sync(0xffffffffu, sl1,  o);
            slm1 += __shfl_xor_sync(0xffffffffu, slm1, o);
        }
        l0 = l0*f0 + sl0;  lm0 = lm0*f0 + slm0;  m0 = mn0;
        l1 = l1*f1 + sl1;  lm1 = lm1*f1 + slm1;  m1 = mn1;
#pragma unroll
        for (int nt = 0; nt < 8; nt++) {
            O[nt][0] *= f0; O[nt][1] *= f0; O[nt][2] *= f1; O[nt][3] *= f1;
        }

        // ---- O += P @ V : group 2 d-tile pairs, product-outer passes ----
#pragma unroll
        for (int kc = 0; kc < 8; kc++) {
            uint32_t aPh[4], aPl[4];
            split_pair(S[2*kc][0],   S[2*kc][1],   aPh[0], aPl[0]);
            split_pair(S[2*kc][2],   S[2*kc][3],   aPh[1], aPl[1]);
            split_pair(S[2*kc+1][0], S[2*kc+1][1], aPh[2], aPl[2]);
            split_pair(S[2*kc+1][2], S[2*kc+1][3], aPh[3], aPl[3]);
#pragma unroll
            for (int pg = 0; pg < 2; pg++) {
                uint32_t vh[2][4], vl[2][4];
#pragma unroll
                for (int j = 0; j < 2; j++) {
                    const int p = pg*2 + j;
                    const uint32_t vo = SWZ128((uint32_t)((kc*16 + (lane & 15))*128 + p*32 + (lane >> 4)*16));
                    LDMX4T(vh[j], st + 2u*16384u + vo);
                    LDMX4T(vl[j], st + 3u*16384u + vo);
                }
                // passes of 4 independent MMAs (O[2p],O[2p+1] for 2 p's)
#pragma unroll
                for (int j = 0; j < 2; j++) {
                    const int p = pg*2 + j;
                    MMA2(O[2*p], O[2*p+1], aPh, vh[j]);
                }
#pragma unroll
                for (int j = 0; j < 2; j++) {
                    const int p = pg*2 + j;
                    MMA2(O[2*p], O[2*p+1], aPh, vl[j]);
                }
#pragma unroll
                for (int j = 0; j < 2; j++) {
                    const int p = pg*2 + j;
                    MMA2(O[2*p], O[2*p+1], aPl, vh[j]);
                }
            }
        }

        __syncthreads();
        if (i + 2 < 8)
            load_kv(st, Kh_, Kl_, Vh_, Vl_, Kmask, bh, b, (i + 2)*128, tid);
    }

    // ---- epilogue ----
    const int r0 = q0 + (wid << 4) + (lane >> 2);
    const float qm0 = Qmask[(size_t)b*SEQ + r0];
    const float qm1 = Qmask[(size_t)b*SEQ + r0 + 8];
    const float inv0 = qm0 / (lm0 + l0*SZTERM);
    const float inv1 = qm1 / (lm1 + l1*SZTERM);
    const size_t base0 = ((size_t)b*SEQ + r0)*HIDDEN + h*DHEAD + 2*(lane & 3);
    const size_t base1 = base0 + (size_t)8*HIDDEN;
#pragma unroll
    for (int nt = 0; nt < 8; nt++) {
        *(float2*)&Ctx[base0 + nt*8] = make_float2(O[nt][0]*inv0, O[nt][1]*inv0);
        *(float2*)&Ctx[base1 + nt*8] = make_float2(O[nt][2]*inv1, O[nt][3]*inv1);
    }
}

// ---------------- launch ----------------
extern "C" void kernel_launch(void* const* d_in, const int* in_sizes, int n_in,
                              void* d_out, int out_size)
{
    const float* Q   = (const float*)d_in[0];
    const float* K   = (const float*)d_in[1];
    const float* V   = (const float*)d_in[2];
    const float* Qm  = (const float*)d_in[3];
    const float* Km  = (const float*)d_in[4];
    const float* Wq  = (const float*)d_in[5];
    const float* bq  = (const float*)d_in[6];
    const float* Wk  = (const float*)d_in[7];
    const float* bk  = (const float*)d_in[8];
    const float* Wv  = (const float*)d_in[9];
    const float* bv  = (const float*)d_in[10];
    const float* Wo  = (const float*)d_in[11];
    const float* bo  = (const float*)d_in[12];
    float* out = (float*)d_out;

    float *gctx;
    __nv_bfloat16 *ah, *al, *wh, *wl, *qh, *ql, *kh, *kl, *vh, *vl;
    cudaGetSymbolAddress((void**)&gctx, g_ctx);
    cudaGetSymbolAddress((void**)&ah,   g_ah);
    cudaGetSymbolAddress((void**)&al,   g_al);
    cudaGetSymbolAddress((void**)&wh,   g_wh);
    cudaGetSymbolAddress((void**)&wl,   g_wl);
    cudaGetSymbolAddress((void**)&qh,   g_qh);
    cudaGetSymbolAddress((void**)&ql,   g_ql);
    cudaGetSymbolAddress((void**)&kh,   g_kh);
    cudaGetSymbolAddress((void**)&kl,   g_kl);
    cudaGetSymbolAddress((void**)&vh,   g_vh);
    cudaGetSymbolAddress((void**)&vl,   g_vl);

    cudaFuncSetAttribute(tcgemm, cudaFuncAttributeMaxDynamicSharedMemorySize, (int)TC_SMEM);
    cudaFuncSetAttribute(flash_mma, cudaFuncAttributeMaxDynamicSharedMemorySize, (int)AT_SMEM);

    const int nA4 = MTOT*HIDDEN/4;
    const int nW4 = HIDDEN*HIDDEN/4;
    dim3 ggrd(HIDDEN/128, MTOT/128);

    // Q projection -> bf16 split [b][h][s][d]
    split_bf16<<<nA4/512, 256>>>(Q, ah, al, nA4);
    split_bf16<<<nW4/512, 256>>>(Wq, wh, wl, nW4);
    tcgemm<<<ggrd, 256, TC_SMEM>>>(ah, al, wh, wl, bq, nullptr, qh, ql, 1);
    // K projection
    split_bf16<<<nA4/512, 256>>>(K, ah, al, nA4);
    split_bf16<<<nW4/512, 256>>>(Wk, wh, wl, nW4);
    tcgemm<<<ggrd, 256, TC_SMEM>>>(ah, al, wh, wl, bk, nullptr, kh, kl, 1);
    // V projection
    split_bf16<<<nA4/512, 256>>>(V, ah, al, nA4);
    split_bf16<<<nW4/512, 256>>>(Wv, wh, wl, nW4);
    tcgemm<<<ggrd, 256, TC_SMEM>>>(ah, al, wh, wl, bv, nullptr, vh, vl, 1);

    // attention (tensor cores)
    dim3 fgrd(SEQ/128, NHEADS, NB);
    flash_mma<<<fgrd, 256, AT_SMEM>>>(qh, ql, kh, kl, vh, vl, Qm, Km, gctx);

    // output projection (fp32 out)
    split_bf16<<<nA4/512, 256>>>(gctx, ah, al, nA4);
    split_bf16<<<nW4/512, 256>>>(Wo, wh, wl, nW4);
    tcgemm<<<ggrd, 256, TC_SMEM>>>(ah, al, wh, wl, bo, out, nullptr, nullptr, 0);

    (void)in_sizes; (void)n_in; (void)out_size;
}

// round 17
// speedup vs baseline: 1.1651x; 1.1651x over previous
#include <cuda_runtime.h>
#include <cuda_bf16.h>
#include <cuda_fp16.h>
#include <cstdint>

#define NB      8
#define SEQ     1024
#define HIDDEN  1024
#define NHEADS  16
#define DHEAD   64
#define MTOT    (NB*SEQ)        // 8192
#define SZTERM  1.024e-5f       // S * ZERO = 1024 * 1e-8

// ---------------- scratch (no allocations allowed) ----------------
__device__ __nv_bfloat16 g_ah[MTOT*HIDDEN];        // GEMM A hi  (later: ctx hi fp16)
__device__ __nv_bfloat16 g_al[MTOT*HIDDEN];        // GEMM A lo  (later: ctx lo fp16)
__device__ __nv_bfloat16 g_wh[HIDDEN*HIDDEN];      // W hi       (later: Wo fp16)
__device__ __nv_bfloat16 g_wl[HIDDEN*HIDDEN];      // W lo
__device__ __nv_bfloat16 g_qh[NB*NHEADS*SEQ*DHEAD];  // [b][h][s][d] splits
__device__ __nv_bfloat16 g_ql[NB*NHEADS*SEQ*DHEAD];
__device__ __nv_bfloat16 g_kh[NB*NHEADS*SEQ*DHEAD];
__device__ __nv_bfloat16 g_kl[NB*NHEADS*SEQ*DHEAD];
__device__ __half        g_vf[NB*NHEADS*SEQ*DHEAD]; // V single fp16

// ================= helpers =================
__device__ __forceinline__ uint32_t smem_u32(const void* p) {
    uint32_t a;
    asm("{ .reg .u64 t; cvta.to.shared.u64 t, %1; cvt.u32.u64 %0, t; }" : "=r"(a) : "l"(p));
    return a;
}
__device__ __forceinline__ void cp_async16(uint32_t dst, const void* src) {
    asm volatile("cp.async.cg.shared.global [%0], [%1], 16;" :: "r"(dst), "l"(src) : "memory");
}
#define CP_COMMIT()  asm volatile("cp.async.commit_group;" ::: "memory")
#define CP_WAIT(n)   asm volatile("cp.async.wait_group %0;" :: "n"(n) : "memory")

#define SWZ128(o) ((o) ^ (((o) >> 3) & 0x70))

#define LDMX4(r, a) \
    asm volatile("ldmatrix.sync.aligned.m8n8.x4.shared.b16 {%0,%1,%2,%3}, [%4];" \
        : "=r"((r)[0]), "=r"((r)[1]), "=r"((r)[2]), "=r"((r)[3]) : "r"(a))

#define LDMX4T(r, a) \
    asm volatile("ldmatrix.sync.aligned.m8n8.x4.trans.shared.b16 {%0,%1,%2,%3}, [%4];" \
        : "=r"((r)[0]), "=r"((r)[1]), "=r"((r)[2]), "=r"((r)[3]) : "r"(a))

#define MMA16816(c, a, b) \
    asm volatile("mma.sync.aligned.m16n8k16.row.col.f32.bf16.bf16.f32 " \
        "{%0,%1,%2,%3}, {%4,%5,%6,%7}, {%8,%9}, {%0,%1,%2,%3};" \
        : "+f"((c)[0]), "+f"((c)[1]), "+f"((c)[2]), "+f"((c)[3]) \
        : "r"((a)[0]), "r"((a)[1]), "r"((a)[2]), "r"((a)[3]), "r"((b)[0]), "r"((b)[1]))

#define MMAH16816(c, a, b) \
    asm volatile("mma.sync.aligned.m16n8k16.row.col.f32.f16.f16.f32 " \
        "{%0,%1,%2,%3}, {%4,%5,%6,%7}, {%8,%9}, {%0,%1,%2,%3};" \
        : "+f"((c)[0]), "+f"((c)[1]), "+f"((c)[2]), "+f"((c)[3]) \
        : "r"((a)[0]), "r"((a)[1]), "r"((a)[2]), "r"((a)[3]), "r"((b)[0]), "r"((b)[1]))

#define MMA2(c0, c1, a, r4) do { \
    uint32_t _b0[2] = {(r4)[0], (r4)[1]}; \
    uint32_t _b1[2] = {(r4)[2], (r4)[3]}; \
    MMA16816(c0, a, _b0); \
    MMA16816(c1, a, _b1); \
} while (0)

#define MMAH2(c0, c1, a, r4) do { \
    uint32_t _b0[2] = {(r4)[0], (r4)[1]}; \
    uint32_t _b1[2] = {(r4)[2], (r4)[3]}; \
    MMAH16816(c0, a, _b0); \
    MMAH16816(c1, a, _b1); \
} while (0)

__device__ __forceinline__ uint32_t pack_h2(float x, float y) {
    __half2 t = __floats2half2_rn(x, y);
    return *(uint32_t*)&t;
}

// ================= fp32 -> bf16 hi/lo split =================
__global__ __launch_bounds__(256)
void split_bf16(const float* __restrict__ x, __nv_bfloat16* __restrict__ hi,
                __nv_bfloat16* __restrict__ lo, int n4)
{
    const int i0 = blockIdx.x * 512 + threadIdx.x;
#pragma unroll
    for (int r = 0; r < 2; r++) {
        const int i = i0 + r*256;
        if (i >= n4) return;
        float4 v = ((const float4*)x)[i];
        float f[4] = {v.x, v.y, v.z, v.w};
        __nv_bfloat16 h[4], l[4];
#pragma unroll
        for (int j = 0; j < 4; j++) {
            h[j] = __float2bfloat16_rn(f[j]);
            l[j] = __float2bfloat16_rn(f[j] - __bfloat162float(h[j]));
        }
        __nv_bfloat162* H = (__nv_bfloat162*)hi;
        __nv_bfloat162* L = (__nv_bfloat162*)lo;
        H[2*i]   = __halves2bfloat162(h[0], h[1]);
        H[2*i+1] = __halves2bfloat162(h[2], h[3]);
        L[2*i]   = __halves2bfloat162(l[0], l[1]);
        L[2*i+1] = __halves2bfloat162(l[2], l[3]);
    }
}

// ================= fp32 -> fp16 convert =================
__global__ __launch_bounds__(256)
void conv_f16(const float* __restrict__ x, __half* __restrict__ y, int n4)
{
    const int i0 = blockIdx.x * 512 + threadIdx.x;
#pragma unroll
    for (int r = 0; r < 2; r++) {
        const int i = i0 + r*256;
        if (i >= n4) return;
        float4 v = ((const float4*)x)[i];
        __half2* Y = (__half2*)y;
        Y[2*i]   = __floats2half2_rn(v.x, v.y);
        Y[2*i+1] = __floats2half2_rn(v.z, v.w);
    }
}

// ================= bf16 3-product GEMM: C = A[M,K] @ W[N,K]^T + bias =================
// mode 0: fp32 [m][n];  mode 1: bf16 hi/lo split [b][h][s][d];  mode 3: fp16 single [b][h][s][d]
#define TILE_BYTES 16384u
#define STAGE_BYTES (4u*TILE_BYTES)
#define TC_SMEM (3u*STAGE_BYTES)         // 196608

__device__ __forceinline__ void load_chunk(
    const __nv_bfloat16* __restrict__ Ah, const __nv_bfloat16* __restrict__ Al,
    const __nv_bfloat16* __restrict__ Bh, const __nv_bfloat16* __restrict__ Bl,
    int m0, int n0, int kc, uint32_t buf, int tid)
{
#pragma unroll
    for (int it = 0; it < 4; it++) {
        const int idx = tid + it*256;
        const int row = idx >> 3;
        const int c   = idx & 7;
        const uint32_t off = SWZ128((uint32_t)(row*128 + c*16));
        const size_t arow = (size_t)(m0 + row) * HIDDEN + kc*64 + c*8;
        const size_t brow = (size_t)(n0 + row) * HIDDEN + kc*64 + c*8;
        cp_async16(buf + 0*TILE_BYTES + off, Ah + arow);
        cp_async16(buf + 1*TILE_BYTES + off, Al + arow);
        cp_async16(buf + 2*TILE_BYTES + off, Bh + brow);
        cp_async16(buf + 3*TILE_BYTES + off, Bl + brow);
    }
    CP_COMMIT();
}

__global__ __launch_bounds__(256, 1)
void tcgemm(const __nv_bfloat16* __restrict__ Ah, const __nv_bfloat16* __restrict__ Al,
            const __nv_bfloat16* __restrict__ Bh, const __nv_bfloat16* __restrict__ Bl,
            const float* __restrict__ bias, float* __restrict__ Cf,
            __nv_bfloat16* __restrict__ Ch, __nv_bfloat16* __restrict__ Cl,
            __half* __restrict__ Hf, int mode)
{
    extern __shared__ char smem[];
    const uint32_t sb = smem_u32(smem);
    const int tid  = threadIdx.x;
    const int lane = tid & 31;
    const int wid  = tid >> 5;
    const int m0 = blockIdx.y * 128;
    const int n0 = blockIdx.x * 128;
    const int wm = (wid & 1) * 64;
    const int wn = (wid >> 1) * 32;

    const int a_row = wm + (lane & 15);
    const int a_kh  = (lane >> 4) * 16;
    const int b_rr  = (lane & 7) + ((lane >> 4) << 3);
    const int b_kh  = (lane & 8) ? 16 : 0;

    float acc[4][4][4];
#pragma unroll
    for (int mt = 0; mt < 4; mt++)
#pragma unroll
        for (int nt = 0; nt < 4; nt++)
#pragma unroll
            for (int j = 0; j < 4; j++) acc[mt][nt][j] = 0.0f;

#pragma unroll
    for (int s = 0; s < 3; s++)
        load_chunk(Ah, Al, Bh, Bl, m0, n0, s, sb + s*STAGE_BYTES, tid);

    for (int i = 0; i < 16; i++) {
        if (i < 14)       CP_WAIT(2);
        else if (i == 14) CP_WAIT(1);
        else              CP_WAIT(0);
        __syncthreads();

        const uint32_t buf = sb + (uint32_t)(i % 3) * STAGE_BYTES;
        const uint32_t bAh = buf;
        const uint32_t bAl = buf + 1*TILE_BYTES;
        const uint32_t bBh = buf + 2*TILE_BYTES;
        const uint32_t bBl = buf + 3*TILE_BYTES;

#pragma unroll
        for (int ks = 0; ks < 4; ks++) {
            const int kb = ks * 32;
            uint32_t aH[4][4], aL[4][4], bH[4][2], bL[4][2];
#pragma unroll
            for (int mt = 0; mt < 4; mt++) {
                const uint32_t ao = SWZ128((uint32_t)((a_row + mt*16)*128 + kb + a_kh));
                LDMX4(aH[mt], bAh + ao);
                LDMX4(aL[mt], bAl + ao);
            }
#pragma unroll
            for (int p = 0; p < 2; p++) {
                const uint32_t bo = SWZ128((uint32_t)((wn + p*16 + b_rr)*128 + kb + b_kh));
                uint32_t rh[4], rl[4];
                LDMX4(rh, bBh + bo);
                LDMX4(rl, bBl + bo);
                bH[2*p][0] = rh[0]; bH[2*p][1] = rh[1];
                bH[2*p+1][0] = rh[2]; bH[2*p+1][1] = rh[3];
                bL[2*p][0] = rl[0]; bL[2*p][1] = rl[1];
                bL[2*p+1][0] = rl[2]; bL[2*p+1][1] = rl[3];
            }
#pragma unroll
            for (int mt = 0; mt < 4; mt++)
#pragma unroll
                for (int nt = 0; nt < 4; nt++)
                    MMA16816(acc[mt][nt], aH[mt], bH[nt]);
#pragma unroll
            for (int mt = 0; mt < 4; mt++)
#pragma unroll
                for (int nt = 0; nt < 4; nt++)
                    MMA16816(acc[mt][nt], aH[mt], bL[nt]);
#pragma unroll
            for (int mt = 0; mt < 4; mt++)
#pragma unroll
                for (int nt = 0; nt < 4; nt++)
                    MMA16816(acc[mt][nt], aL[mt], bH[nt]);
        }
        __syncthreads();
        if (i + 3 < 16)
            load_chunk(Ah, Al, Bh, Bl, m0, n0, i + 3, buf, tid);
    }

#pragma unroll
    for (int mt = 0; mt < 4; mt++) {
        const int r0 = wm + mt*16 + (lane >> 2);
#pragma unroll
        for (int half = 0; half < 2; half++) {
            const int m  = m0 + r0 + half*8;
            const int bb = m >> 10;
            const int ss = m & 1023;
#pragma unroll
            for (int nt = 0; nt < 4; nt++) {
                const int n = n0 + wn + nt*8 + 2*(lane & 3);
                float v0 = acc[mt][nt][half*2+0] + bias[n];
                float v1 = acc[mt][nt][half*2+1] + bias[n+1];
                if (mode == 1) {
                    const int hh = n >> 6;
                    const int d  = n & 63;
                    const size_t idx = (((size_t)(bb*NHEADS + hh))*SEQ + ss)*DHEAD + d;
                    __nv_bfloat16 h0 = __float2bfloat16_rn(v0);
                    __nv_bfloat16 h1 = __float2bfloat16_rn(v1);
                    *(__nv_bfloat162*)(Ch + idx) = __halves2bfloat162(h0, h1);
                    *(__nv_bfloat162*)(Cl + idx) = __halves2bfloat162(
                        __float2bfloat16_rn(v0 - __bfloat162float(h0)),
                        __float2bfloat16_rn(v1 - __bfloat162float(h1)));
                } else if (mode == 3) {
                    const int hh = n >> 6;
                    const int d  = n & 63;
                    const size_t idx = (((size_t)(bb*NHEADS + hh))*SEQ + ss)*DHEAD + d;
                    *(__half2*)(Hf + idx) = __floats2half2_rn(v0, v1);
                } else {
                    *(float2*)(Cf + (size_t)m * HIDDEN + n) = make_float2(v0, v1);
                }
            }
        }
    }
}

// ================= fp16 2-product GEMM: C = (Ah+Al)[M,K] @ W[N,K]^T + bias =================
// A split fp16 h+l, B single fp16; fp32 output.
#define STAGE2_BYTES (3u*TILE_BYTES)
#define TC2_SMEM (3u*STAGE2_BYTES)        // 147456

__device__ __forceinline__ void load_chunk2(
    const __half* __restrict__ Ah, const __half* __restrict__ Al,
    const __half* __restrict__ B,
    int m0, int n0, int kc, uint32_t buf, int tid)
{
#pragma unroll
    for (int it = 0; it < 4; it++) {
        const int idx = tid + it*256;
        const int row = idx >> 3;
        const int c   = idx & 7;
        const uint32_t off = SWZ128((uint32_t)(row*128 + c*16));
        const size_t arow = (size_t)(m0 + row) * HIDDEN + kc*64 + c*8;
        const size_t brow = (size_t)(n0 + row) * HIDDEN + kc*64 + c*8;
        cp_async16(buf + 0*TILE_BYTES + off, Ah + arow);
        cp_async16(buf + 1*TILE_BYTES + off, Al + arow);
        cp_async16(buf + 2*TILE_BYTES + off, B  + brow);
    }
    CP_COMMIT();
}

__global__ __launch_bounds__(256, 1)
void tcgemm2(const __half* __restrict__ Ah, const __half* __restrict__ Al,
             const __half* __restrict__ B,
             const float* __restrict__ bias, float* __restrict__ Cf)
{
    extern __shared__ char smem[];
    const uint32_t sb = smem_u32(smem);
    const int tid  = threadIdx.x;
    const int lane = tid & 31;
    const int wid  = tid >> 5;
    const int m0 = blockIdx.y * 128;
    const int n0 = blockIdx.x * 128;
    const int wm = (wid & 1) * 64;
    const int wn = (wid >> 1) * 32;

    const int a_row = wm + (lane & 15);
    const int a_kh  = (lane >> 4) * 16;
    const int b_rr  = (lane & 7) + ((lane >> 4) << 3);
    const int b_kh  = (lane & 8) ? 16 : 0;

    float acc[4][4][4];
#pragma unroll
    for (int mt = 0; mt < 4; mt++)
#pragma unroll
        for (int nt = 0; nt < 4; nt++)
#pragma unroll
            for (int j = 0; j < 4; j++) acc[mt][nt][j] = 0.0f;

#pragma unroll
    for (int s = 0; s < 3; s++)
        load_chunk2(Ah, Al, B, m0, n0, s, sb + s*STAGE2_BYTES, tid);

    for (int i = 0; i < 16; i++) {
        if (i < 14)       CP_WAIT(2);
        else if (i == 14) CP_WAIT(1);
        else              CP_WAIT(0);
        __syncthreads();

        const uint32_t buf = sb + (uint32_t)(i % 3) * STAGE2_BYTES;
        const uint32_t bAh = buf;
        const uint32_t bAl = buf + 1*TILE_BYTES;
        const uint32_t bB  = buf + 2*TILE_BYTES;

#pragma unroll
        for (int ks = 0; ks < 4; ks++) {
            const int kb = ks * 32;
            uint32_t aH[4][4], aL[4][4], bF[4][2];
#pragma unroll
            for (int mt = 0; mt < 4; mt++) {
                const uint32_t ao = SWZ128((uint32_t)((a_row + mt*16)*128 + kb + a_kh));
                LDMX4(aH[mt], bAh + ao);
                LDMX4(aL[mt], bAl + ao);
            }
#pragma unroll
            for (int p = 0; p < 2; p++) {
                const uint32_t bo = SWZ128((uint32_t)((wn + p*16 + b_rr)*128 + kb + b_kh));
                uint32_t rh[4];
                LDMX4(rh, bB + bo);
                bF[2*p][0] = rh[0]; bF[2*p][1] = rh[1];
                bF[2*p+1][0] = rh[2]; bF[2*p+1][1] = rh[3];
            }
#pragma unroll
            for (int mt = 0; mt < 4; mt++)
#pragma unroll
                for (int nt = 0; nt < 4; nt++)
                    MMAH16816(acc[mt][nt], aH[mt], bF[nt]);
#pragma unroll
            for (int mt = 0; mt < 4; mt++)
#pragma unroll
                for (int nt = 0; nt < 4; nt++)
                    MMAH16816(acc[mt][nt], aL[mt], bF[nt]);
        }
        __syncthreads();
        if (i + 3 < 16)
            load_chunk2(Ah, Al, B, m0, n0, i + 3, buf, tid);
    }

#pragma unroll
    for (int mt = 0; mt < 4; mt++) {
        const int r0 = wm + mt*16 + (lane >> 2);
#pragma unroll
        for (int half = 0; half < 2; half++) {
            const int m  = m0 + r0 + half*8;
#pragma unroll
            for (int nt = 0; nt < 4; nt++) {
                const int n = n0 + wn + nt*8 + 2*(lane & 3);
                float v0 = acc[mt][nt][half*2+0] + bias[n];
                float v1 = acc[mt][nt][half*2+1] + bias[n+1];
                *(float2*)(Cf + (size_t)m * HIDDEN + n) = make_float2(v0, v1);
            }
        }
    }
}

// ================= tensor-core flash attention =================
// CTA: 128 q rows x one (b,h). 8 warps, warp = 16 q rows x 128 keys.
// QK^T: bf16 3-product.  PV: fp16 single product.
// stage: Kh 16KB + Kl 16KB + Vf(fp16) 16KB + Kmask 512B = 49664
#define AT_STAGE 49664u
#define AT_SMEM  (32768u + 2u*AT_STAGE)   // 132096

__device__ __forceinline__ void load_kv(
    uint32_t st, const __nv_bfloat16* __restrict__ Kh_, const __nv_bfloat16* __restrict__ Kl_,
    const __half* __restrict__ Vf_,
    const float* __restrict__ Kmask, int bh, int b, int kt, int tid)
{
    const size_t koff = ((size_t)bh*SEQ + kt)*DHEAD;
#pragma unroll
    for (int it = 0; it < 4; it++) {
        const int idx = tid + it*256;
        const int row = idx >> 3;
        const int c   = idx & 7;
        const uint32_t off = SWZ128((uint32_t)(row*128 + c*16));
        const size_t src = koff + (size_t)row*DHEAD + c*8;
        cp_async16(st + 0u*16384u + off, Kh_ + src);
        cp_async16(st + 1u*16384u + off, Kl_ + src);
        cp_async16(st + 2u*16384u + off, Vf_ + src);
    }
    if (tid < 32)
        cp_async16(st + 49152u + tid*16, Kmask + (size_t)b*SEQ + kt + tid*4);
    CP_COMMIT();
}

__global__ __launch_bounds__(256, 1)
void flash_mma(const __nv_bfloat16* __restrict__ Qh_, const __nv_bfloat16* __restrict__ Ql_,
               const __nv_bfloat16* __restrict__ Kh_, const __nv_bfloat16* __restrict__ Kl_,
               const __half* __restrict__ Vf_,
               const float* __restrict__ Qmask, const float* __restrict__ Kmask,
               __half* __restrict__ CtxH, __half* __restrict__ CtxL)
{
    extern __shared__ char smem[];
    const uint32_t sb = smem_u32(smem);
    const int tid  = threadIdx.x;
    const int lane = tid & 31;
    const int wid  = tid >> 5;
    const int q0 = blockIdx.x * 128;
    const int h  = blockIdx.y;
    const int b  = blockIdx.z;
    const int bh = b*NHEADS + h;

    {
        const size_t qoff = ((size_t)bh*SEQ + q0)*DHEAD;
#pragma unroll
        for (int it = 0; it < 4; it++) {
            const int idx = tid + it*256;
            const int row = idx >> 3;
            const int c   = idx & 7;
            const uint32_t off = SWZ128((uint32_t)(row*128 + c*16));
            const size_t src = qoff + (size_t)row*DHEAD + c*8;
            cp_async16(sb + off, Qh_ + src);
            cp_async16(sb + 16384u + off, Ql_ + src);
        }
        CP_COMMIT();
    }
    load_kv(sb + 32768u,            Kh_, Kl_, Vf_, Kmask, bh, b, 0,   tid);
    load_kv(sb + 32768u + AT_STAGE, Kh_, Kl_, Vf_, Kmask, bh, b, 128, tid);

    const int a_row = (wid << 4) + (lane & 15);
    const int a_kh  = (lane >> 4) * 16;
    const int b_rr  = (lane & 7) + ((lane >> 4) << 3);
    const int b_kh  = (lane & 8) ? 16 : 0;

    uint32_t qH[4][4], qL[4][4];
    float O[8][4];
#pragma unroll
    for (int nt = 0; nt < 8; nt++)
#pragma unroll
        for (int j = 0; j < 4; j++) O[nt][j] = 0.0f;
    float m0 = -1e30f, m1 = -1e30f, l0 = 0.f, l1 = 0.f, lm0 = 0.f, lm1 = 0.f;

    for (int i = 0; i < 8; i++) {
        CP_WAIT(1);
        __syncthreads();

        if (i == 0) {
#pragma unroll
            for (int ks = 0; ks < 4; ks++) {
                const uint32_t ao = SWZ128((uint32_t)(a_row*128 + ks*32 + a_kh));
                LDMX4(qH[ks], sb + ao);
                LDMX4(qL[ks], sb + 16384u + ao);
            }
        }

        const uint32_t st = sb + 32768u + (uint32_t)(i & 1)*AT_STAGE;
        const float* Kms = (const float*)(smem + 32768u + (uint32_t)(i & 1)*AT_STAGE + 49152u);

        // ---- S = QhKh + QhKl + QlKh ----
        float S[16][4];
#pragma unroll
        for (int nt = 0; nt < 16; nt++)
#pragma unroll
            for (int j = 0; j < 4; j++) S[nt][j] = 0.0f;

#pragma unroll
        for (int ks = 0; ks < 4; ks++) {
#pragma unroll
            for (int pg = 0; pg < 2; pg++) {
                uint32_t rh[4][4], rl[4][4];
#pragma unroll
                for (int j = 0; j < 4; j++) {
                    const int p = pg*4 + j;
                    const uint32_t bo = SWZ128((uint32_t)((p*16 + b_rr)*128 + ks*32 + b_kh));
                    LDMX4(rh[j], st + bo);
                    LDMX4(rl[j], st + 16384u + bo);
                }
#pragma unroll
                for (int j = 0; j < 4; j++) {
                    const int p = pg*4 + j;
                    MMA2(S[2*p], S[2*p+1], qH[ks], rh[j]);
                }
#pragma unroll
                for (int j = 0; j < 4; j++) {
                    const int p = pg*4 + j;
                    MMA2(S[2*p], S[2*p+1], qH[ks], rl[j]);
                }
#pragma unroll
                for (int j = 0; j < 4; j++) {
                    const int p = pg*4 + j;
                    MMA2(S[2*p], S[2*p+1], qL[ks], rh[j]);
                }
            }
        }

        // ---- online softmax ----
        float mx0 = -1e30f, mx1 = -1e30f;
#pragma unroll
        for (int nt = 0; nt < 16; nt++) {
            S[nt][0] *= 8.0f; S[nt][1] *= 8.0f; S[nt][2] *= 8.0f; S[nt][3] *= 8.0f;
            mx0 = fmaxf(mx0, fmaxf(S[nt][0], S[nt][1]));
            mx1 = fmaxf(mx1, fmaxf(S[nt][2], S[nt][3]));
        }
        mx0 = fmaxf(mx0, __shfl_xor_sync(0xffffffffu, mx0, 1));
        mx0 = fmaxf(mx0, __shfl_xor_sync(0xffffffffu, mx0, 2));
        mx1 = fmaxf(mx1, __shfl_xor_sync(0xffffffffu, mx1, 1));
        mx1 = fmaxf(mx1, __shfl_xor_sync(0xffffffffu, mx1, 2));

        const float mn0 = fmaxf(m0, mx0), mn1 = fmaxf(m1, mx1);
        const float f0 = __expf(m0 - mn0), f1 = __expf(m1 - mn1);
        float sl0 = 0.f, slm0 = 0.f, sl1 = 0.f, slm1 = 0.f;
#pragma unroll
        for (int nt = 0; nt < 16; nt++) {
            const float kma = Kms[nt*8 + 2*(lane & 3)];
            const float kmb = Kms[nt*8 + 2*(lane & 3) + 1];
            float e0 = __expf(S[nt][0] - mn0); sl0 += e0; float p0 = e0*kma; slm0 += p0; S[nt][0] = p0;
            float e1 = __expf(S[nt][1] - mn0); sl0 += e1; float p1 = e1*kmb; slm0 += p1; S[nt][1] = p1;
            float e2 = __expf(S[nt][2] - mn1); sl1 += e2; float p2 = e2*kma; slm1 += p2; S[nt][2] = p2;
            float e3 = __expf(S[nt][3] - mn1); sl1 += e3; float p3 = e3*kmb; slm1 += p3; S[nt][3] = p3;
        }
#pragma unroll
        for (int o = 1; o <= 2; o <<= 1) {
            sl0  += __shfl_xor_sync(0xffffffffu, sl0,  o);
            slm0 += __shfl_xor_sync(0xffffffffu, slm0, o);
            sl1  += __shfl_xor_sync(0xffffffffu, sl1,  o);
            slm1 += __shfl_xor_sync(0xffffffffu, slm1, o);
        }
        l0 = l0*f0 + sl0;  lm0 = lm0*f0 + slm0;  m0 = mn0;
        l1 = l1*f1 + sl1;  lm1 = lm1*f1 + slm1;  m1 = mn1;
#pragma unroll
        for (int nt = 0; nt < 8; nt++) {
            O[nt][0] *= f0; O[nt][1] *= f0; O[nt][2] *= f1; O[nt][3] *= f1;
        }

        // ---- O += P @ V  (single-product fp16) ----
#pragma unroll
        for (int kc = 0; kc < 8; kc++) {
            uint32_t aP[4];
            aP[0] = pack_h2(S[2*kc][0],   S[2*kc][1]);
            aP[1] = pack_h2(S[2*kc][2],   S[2*kc][3]);
            aP[2] = pack_h2(S[2*kc+1][0], S[2*kc+1][1]);
            aP[3] = pack_h2(S[2*kc+1][2], S[2*kc+1][3]);
            uint32_t vf[4][4];
#pragma unroll
            for (int p = 0; p < 4; p++) {
                const uint32_t vo = SWZ128((uint32_t)((kc*16 + (lane & 15))*128 + p*32 + (lane >> 4)*16));
                LDMX4T(vf[p], st + 2u*16384u + vo);
            }
#pragma unroll
            for (int p = 0; p < 4; p++)
                MMAH2(O[2*p], O[2*p+1], aP, vf[p]);
        }

        __syncthreads();
        if (i + 2 < 8)
            load_kv(st, Kh_, Kl_, Vf_, Kmask, bh, b, (i + 2)*128, tid);
    }

    // ---- epilogue: ctx = Qm*O/(lm + l*S*ZERO), written as fp16 hi/lo split ----
    const int r0 = q0 + (wid << 4) + (lane >> 2);
    const float qm0 = Qmask[(size_t)b*SEQ + r0];
    const float qm1 = Qmask[(size_t)b*SEQ + r0 + 8];
    const float inv0 = qm0 / (lm0 + l0*SZTERM);
    const float inv1 = qm1 / (lm1 + l1*SZTERM);
    const size_t base0 = ((size_t)b*SEQ + r0)*HIDDEN + h*DHEAD + 2*(lane & 3);
    const size_t base1 = base0 + (size_t)8*HIDDEN;
#pragma unroll
    for (int nt = 0; nt < 8; nt++) {
        float v0 = O[nt][0]*inv0, v1 = O[nt][1]*inv0;
        float w0 = O[nt][2]*inv1, w1 = O[nt][3]*inv1;
        __half h0 = __float2half_rn(v0), h1 = __float2half_rn(v1);
        __half g0 = __float2half_rn(w0), g1 = __float2half_rn(w1);
        *(__half2*)(CtxH + base0 + nt*8) = __halves2half2(h0, h1);
        *(__half2*)(CtxL + base0 + nt*8) = __floats2half2_rn(
            v0 - __half2float(h0), v1 - __half2float(h1));
        *(__half2*)(CtxH + base1 + nt*8) = __halves2half2(g0, g1);
        *(__half2*)(CtxL + base1 + nt*8) = __floats2half2_rn(
            w0 - __half2float(g0), w1 - __half2float(g1));
    }
}

// ---------------- launch ----------------
extern "C" void kernel_launch(void* const* d_in, const int* in_sizes, int n_in,
                              void* d_out, int out_size)
{
    const float* Q   = (const float*)d_in[0];
    const float* K   = (const float*)d_in[1];
    const float* V   = (const float*)d_in[2];
    const float* Qm  = (const float*)d_in[3];
    const float* Km  = (const float*)d_in[4];
    const float* Wq  = (const float*)d_in[5];
    const float* bq  = (const float*)d_in[6];
    const float* Wk  = (const float*)d_in[7];
    const float* bk  = (const float*)d_in[8];
    const float* Wv  = (const float*)d_in[9];
    const float* bv  = (const float*)d_in[10];
    const float* Wo  = (const float*)d_in[11];
    const float* bo  = (const float*)d_in[12];
    float* out = (float*)d_out;

    __nv_bfloat16 *ah, *al, *wh, *wl, *qh, *ql, *kh, *kl;
    __half *vf;
    cudaGetSymbolAddress((void**)&ah, g_ah);
    cudaGetSymbolAddress((void**)&al, g_al);
    cudaGetSymbolAddress((void**)&wh, g_wh);
    cudaGetSymbolAddress((void**)&wl, g_wl);
    cudaGetSymbolAddress((void**)&qh, g_qh);
    cudaGetSymbolAddress((void**)&ql, g_ql);
    cudaGetSymbolAddress((void**)&kh, g_kh);
    cudaGetSymbolAddress((void**)&kl, g_kl);
    cudaGetSymbolAddress((void**)&vf, g_vf);

    // fp16 reinterpretations (buffers are dead at the point of reuse)
    __half* cth = (__half*)ah;   // ctx hi (g_ah dead after V projection)
    __half* ctl = (__half*)al;   // ctx lo
    __half* wof = (__half*)wh;   // Wo fp16 (g_wh dead after V projection)

    cudaFuncSetAttribute(tcgemm,  cudaFuncAttributeMaxDynamicSharedMemorySize, (int)TC_SMEM);
    cudaFuncSetAttribute(tcgemm2, cudaFuncAttributeMaxDynamicSharedMemorySize, (int)TC2_SMEM);
    cudaFuncSetAttribute(flash_mma, cudaFuncAttributeMaxDynamicSharedMemorySize, (int)AT_SMEM);

    const int nA4 = MTOT*HIDDEN/4;
    const int nW4 = HIDDEN*HIDDEN/4;
    dim3 ggrd(HIDDEN/128, MTOT/128);

    // Q projection -> bf16 split [b][h][s][d]
    split_bf16<<<nA4/512, 256>>>(Q, ah, al, nA4);
    split_bf16<<<nW4/512, 256>>>(Wq, wh, wl, nW4);
    tcgemm<<<ggrd, 256, TC_SMEM>>>(ah, al, wh, wl, bq, nullptr, qh, ql, nullptr, 1);
    // K projection
    split_bf16<<<nA4/512, 256>>>(K, ah, al, nA4);
    split_bf16<<<nW4/512, 256>>>(Wk, wh, wl, nW4);
    tcgemm<<<ggrd, 256, TC_SMEM>>>(ah, al, wh, wl, bk, nullptr, kh, kl, nullptr, 1);
    // V projection -> fp16 single [b][h][s][d] (accurate 3-product compute, quantize once)
    split_bf16<<<nA4/512, 256>>>(V, ah, al, nA4);
    split_bf16<<<nW4/512, 256>>>(Wv, wh, wl, nW4);
    tcgemm<<<ggrd, 256, TC_SMEM>>>(ah, al, wh, wl, bv, nullptr, nullptr, nullptr, vf, 3);

    // attention: QK bf16 3-product, PV fp16 1-product; ctx emitted as fp16 h/l split
    dim3 fgrd(SEQ/128, NHEADS, NB);
    flash_mma<<<fgrd, 256, AT_SMEM>>>(qh, ql, kh, kl, vf, Qm, Km, cth, ctl);

    // output projection: fp16 2-product (ctx h+l) x Wo fp16
    conv_f16<<<nW4/512, 256>>>(Wo, wof, nW4);
    tcgemm2<<<ggrd, 256, TC2_SMEM>>>(cth, ctl, wof, bo, out);

    (void)in_sizes; (void)n_in; (void)out_size;
}